// round 3
// baseline (speedup 1.0000x reference)
#include <cuda_runtime.h>

typedef unsigned long long ull;

#define MT 4096        // tokens
#define DM 64          // d_model
#define HDD 8          // head dim
#define NLAYER 4
#define DFFN 256
#define LNEPS 1e-5f
#define LOG2E_F 1.4426950408889634f
#define QSCALE 0.35355339059327373f   // 1/sqrt(8)
#define NB 148
#define NT 512

// ---------------- scratch (device globals; no runtime alloc) ----------------
__device__ float g_xbuf[MT*DM];
__device__ float g_x1[MT*DM];
__device__ float g_big[MT*DFFN];
__device__ float g_qh[MT*DM];        // [NH][M][HD], q pre-scaled by QSCALE*LOG2E
__device__ float g_kh[MT*DM];
__device__ float g_vh[MT*DM];
__device__ float g_attn[MT*DM];
__device__ float g_xp[MT*DM];
__device__ float g_hnx[MT];
__device__ float g_hny[MT];
__device__ float g_acc[3];
__device__ unsigned g_bar;

// ---------------- f32x2 helpers ----------------
__device__ __forceinline__ ull fma2(ull a, ull b, ull c) {
    ull d; asm("fma.rn.f32x2 %0, %1, %2, %3;" : "=l"(d) : "l"(a), "l"(b), "l"(c)); return d;
}
__device__ __forceinline__ ull pack2(float a, float b) {
    ull r; asm("mov.b64 %0, {%1, %2};" : "=l"(r) : "f"(a), "f"(b)); return r;
}
__device__ __forceinline__ void unpack2(ull v, float& a, float& b) {
    asm("mov.b64 {%0, %1}, %2;" : "=f"(a), "=f"(b) : "l"(v));
}
__device__ __forceinline__ float ex2f(float x) {
    float r; asm("ex2.approx.f32 %0, %1;" : "=f"(r) : "f"(x)); return r;
}

// ---------------- grid-wide barrier (all NB blocks resident) ----------------
__device__ __forceinline__ void grid_sync(unsigned& epoch) {
    __syncthreads();
    epoch += NB;
    if (threadIdx.x == 0) {
        __threadfence();
        atomicAdd(&g_bar, 1u);
        unsigned v;
        do {
            asm volatile("ld.acquire.gpu.global.u32 %0, [%1];" : "=r"(v) : "l"(&g_bar));
        } while (v < epoch);
    }
    __syncthreads();
}

__global__ void init_kernel() {
    g_bar = 0u;
    g_acc[0] = 0.f; g_acc[1] = 0.f; g_acc[2] = 0.f;
}

// triangular decode for 64x64 symmetric tile grid: idx -> (bi, bj), bj >= bi
__device__ __forceinline__ void tri64(int idx, int& bi, int& bj) {
    float fr = (129.0f - sqrtf(16641.0f - 8.0f * (float)idx)) * 0.5f;
    int r = (int)fr;
    if (r < 0) r = 0; if (r > 63) r = 63;
    while (64 * r - (r * (r - 1)) / 2 > idx) r--;
    while (64 * (r + 1) - ((r + 1) * r) / 2 <= idx) r++;
    bi = r;
    bj = r + (idx - (64 * r - (r * (r - 1)) / 2));
}

__global__ void __launch_bounds__(NT, 1)
mega_kernel(const float* __restrict__ hsi, const float* __restrict__ rgb,
            const float* __restrict__ in_w, const float* __restrict__ in_b,
            const float* __restrict__ ow,   const float* __restrict__ ob,
            const float* __restrict__ l1w,  const float* __restrict__ l1b,
            const float* __restrict__ l2w,  const float* __restrict__ l2b,
            const float* __restrict__ n1w,  const float* __restrict__ n1b,
            const float* __restrict__ n2w,  const float* __restrict__ n2b,
            const float* __restrict__ mask, float* __restrict__ out, int pos)
{
    __shared__ __align__(16) float smf[10240];   // 40KB
    const int tid = threadIdx.x;
    const int bid = blockIdx.x;
    const int tx = tid & 15, ty = tid >> 4;      // 16 x 32 thread grid
    const int w = tid >> 5, lane = tid & 31;
    unsigned epoch = 0;

    float (*As64)[68] = (float(*)[68])smf;                // 64x68
    float (*Ws64)[68] = (float(*)[68])(smf + 4352);       // 64x68
    float (*As32)[68] = (float(*)[68])smf;                // 32x68
    float (*Ws32b)[68] = (float(*)[68])(smf + 2176);      // 64x68 after 32-row A

    for (int layer = 0; layer < NLAYER; layer++) {
        const float* xin = (layer == 0) ? hsi : g_xbuf;
        const float* inw = in_w + layer * 12288;
        const float* inb = in_b + layer * 192;
        const int last = (layer == NLAYER - 1);

        // ===== phase 1: QKV GEMM + head split (192 units of 64 rows) =====
        for (int u = bid; u < 192; u += NB) {
            const int part = u >> 6, rt = u & 63;
            const int r0 = rt * 64, n0 = part * 64;
            __syncthreads();
            for (int t = tid; t < 1024; t += NT) {
                int rr = t >> 4, kq = (t & 15) << 2;
                *(float4*)&As64[rr][kq] = *(const float4*)&xin[(size_t)(r0 + rr) * 64 + kq];
                *(float4*)&Ws64[rr][kq] = *(const float4*)&inw[(size_t)(n0 + rr) * 64 + kq];
            }
            __syncthreads();
            ull acc[2][4];
#pragma unroll
            for (int i = 0; i < 2; i++)
#pragma unroll
                for (int j = 0; j < 4; j++) acc[i][j] = 0ULL;
#pragma unroll 8
            for (int kk = 0; kk < 32; kk++) {
                ull a0 = *(const ull*)&As64[ty * 2][kk * 2];
                ull a1 = *(const ull*)&As64[ty * 2 + 1][kk * 2];
                ull wv[4];
#pragma unroll
                for (int j = 0; j < 4; j++) wv[j] = *(const ull*)&Ws64[tx * 4 + j][kk * 2];
#pragma unroll
                for (int j = 0; j < 4; j++) {
                    acc[0][j] = fma2(a0, wv[j], acc[0][j]);
                    acc[1][j] = fma2(a1, wv[j], acc[1][j]);
                }
            }
            float* dst = (part == 0) ? g_qh : (part == 1) ? g_kh : g_vh;
            const float qs = (part == 0) ? (QSCALE * LOG2E_F) : 1.0f;
            const int cc = tx * 4, h = cc >> 3, d0 = cc & 7;
#pragma unroll
            for (int i = 0; i < 2; i++) {
                int r = r0 + ty * 2 + i;
                float o[4];
#pragma unroll
                for (int j = 0; j < 4; j++) {
                    float lo, hi; unpack2(acc[i][j], lo, hi);
                    o[j] = (lo + hi + inb[n0 + cc + j]) * qs;
                }
                *(float4*)&dst[(size_t)h * MT * HDD + (size_t)r * HDD + d0] =
                    make_float4(o[0], o[1], o[2], o[3]);
            }
        }
        if (layer == 0) {           // rgb half-norms (no dep on x); hidden in this phase
            int idx = bid * NT + tid;
            if (idx < MT) {
                const float4* r = (const float4*)(rgb + (size_t)idx * 64);
                float s = 0.0f;
#pragma unroll
                for (int t = 0; t < 16; t++) {
                    float4 v = r[t];
                    s += v.x * v.x + v.y * v.y + v.z * v.z + v.w * v.w;
                }
                g_hny[idx] = s * (0.5f * LOG2E_F);
            }
        }
        grid_sync(epoch);

        // ===== phase 2: attention (512 units: 64 q-tiles x 8 heads), 16 warps split keys =====
        for (int u = bid; u < 512; u += NB) {
            const int h = u >> 6;
            const int q0 = (u & 63) * 64;
            const float* Qb = g_qh + (size_t)h * MT * HDD;
            const float* Kb = g_kh + (size_t)h * MT * HDD;
            const float* Vb = g_vh + (size_t)h * MT * HDD;

            ull q[2][4], o[2][4];
            float l[2];
#pragma unroll
            for (int i = 0; i < 2; i++) {
                int qm = q0 + lane + 32 * i;
                const ull* qr = (const ull*)(Qb + (size_t)qm * 8);
#pragma unroll
                for (int j = 0; j < 4; j++) { q[i][j] = qr[j]; o[i][j] = 0ULL; }
                l[i] = 0.0f;
            }

            __syncthreads();                 // protect smem reuse vs previous unit
            float* ksw = smf + w * 512;      // 32 keys: K 256 floats + V 256 floats
            float* vsw = ksw + 256;

            for (int kt = w; kt < 128; kt += 16) {
                __syncwarp();
                const float4* Ks = (const float4*)(Kb + (size_t)kt * 256);
                const float4* Vs = (const float4*)(Vb + (size_t)kt * 256);
#pragma unroll
                for (int u2 = lane; u2 < 64; u2 += 32) {
                    ((float4*)ksw)[u2] = Ks[u2];
                    ((float4*)vsw)[u2] = Vs[u2];
                }
                __syncwarp();
                const ull* kq = (const ull*)ksw;
                const ull* vq = (const ull*)vsw;
#pragma unroll 4
                for (int j = 0; j < 32; j++) {
                    ull k0 = kq[4*j], k1 = kq[4*j+1], k2 = kq[4*j+2], k3 = kq[4*j+3];
                    ull v0 = vq[4*j], v1 = vq[4*j+1], v2 = vq[4*j+2], v3 = vq[4*j+3];
#pragma unroll
                    for (int i = 0; i < 2; i++) {
                        ull s0 = fma2(q[i][0], k0, fma2(q[i][2], k2, 0ULL));
                        ull s1 = fma2(q[i][1], k1, fma2(q[i][3], k3, 0ULL));
                        float a0, b0, a1, b1;
                        unpack2(s0, a0, b0); unpack2(s1, a1, b1);
                        float p = ex2f((a0 + a1) + (b0 + b1));
                        l[i] += p;
                        ull pp = pack2(p, p);
                        o[i][0] = fma2(pp, v0, o[i][0]);
                        o[i][1] = fma2(pp, v1, o[i][1]);
                        o[i][2] = fma2(pp, v2, o[i][2]);
                        o[i][3] = fma2(pp, v3, o[i][3]);
                    }
                }
            }

            __syncthreads();
            float* red  = smf;               // [16][64][8]
            float* lred = smf + 8192;        // [16][64]
#pragma unroll
            for (int i = 0; i < 2; i++) {
                int ql = lane + 32 * i;
#pragma unroll
                for (int jj = 0; jj < 4; jj++) {
                    float a, b; unpack2(o[i][jj], a, b);
                    red[(w * 64 + ql) * 8 + 2 * jj]     = a;
                    red[(w * 64 + ql) * 8 + 2 * jj + 1] = b;
                }
                lred[w * 64 + ql] = l[i];
            }
            __syncthreads();
            if (tid < 64) {
                int qm = q0 + tid;
                float ls = 0.0f;
#pragma unroll
                for (int ww = 0; ww < 16; ww++) ls += lred[ww * 64 + tid];
                float inv = 1.0f / ls;
#pragma unroll
                for (int d = 0; d < 8; d++) {
                    float s = 0.0f;
#pragma unroll
                    for (int ww = 0; ww < 16; ww++) s += red[(ww * 64 + tid) * 8 + d];
                    g_attn[(size_t)qm * 64 + h * 8 + d] = s * inv;
                }
            }
        }
        grid_sync(epoch);

        // ===== phase 3: out-proj + residual + LN1 (128 units of 32 rows) =====
        for (int u = bid; u < 128; u += NB) {
            const int r0 = u * 32;
            __syncthreads();
            for (int t = tid; t < 512; t += NT) {
                int rr = t >> 4, kq = (t & 15) << 2;
                *(float4*)&As32[rr][kq] = *(const float4*)&g_attn[(size_t)(r0 + rr) * 64 + kq];
            }
            for (int t = tid; t < 1024; t += NT) {
                int rr = t >> 4, kq = (t & 15) << 2;
                *(float4*)&Ws32b[rr][kq] = *(const float4*)&ow[(size_t)(layer * 64 + rr) * 64 + kq];
            }
            __syncthreads();
            ull acc[4] = {0ULL, 0ULL, 0ULL, 0ULL};
#pragma unroll 8
            for (int kk = 0; kk < 32; kk++) {
                ull a = *(const ull*)&As32[ty][kk * 2];
#pragma unroll
                for (int j = 0; j < 4; j++)
                    acc[j] = fma2(a, *(const ull*)&Ws32b[tx * 4 + j][kk * 2], acc[j]);
            }
            int r = r0 + ty;
            float v[4];
#pragma unroll
            for (int j = 0; j < 4; j++) {
                int n = tx * 4 + j;
                float lo, hi; unpack2(acc[j], lo, hi);
                v[j] = lo + hi + ob[layer * 64 + n] + xin[(size_t)r * 64 + n];
            }
            float s = v[0] + v[1] + v[2] + v[3];
#pragma unroll
            for (int ml = 8; ml; ml >>= 1) s += __shfl_xor_sync(0xffffffffu, s, ml, 16);
            float mu = s * (1.0f / 64.0f);
            float qv = 0.0f;
#pragma unroll
            for (int j = 0; j < 4; j++) { float d = v[j] - mu; qv += d * d; }
#pragma unroll
            for (int ml = 8; ml; ml >>= 1) qv += __shfl_xor_sync(0xffffffffu, qv, ml, 16);
            float inv = rsqrtf(qv * (1.0f / 64.0f) + LNEPS);
            float o[4];
#pragma unroll
            for (int j = 0; j < 4; j++) {
                int n = tx * 4 + j;
                o[j] = (v[j] - mu) * inv * n1w[layer * 64 + n] + n1b[layer * 64 + n];
            }
            *(float4*)&g_x1[(size_t)r * 64 + tx * 4] = make_float4(o[0], o[1], o[2], o[3]);
        }
        grid_sync(epoch);

        // ===== phase 4: FF1 (256 units of 64 rows x 64 cols) + relu =====
        for (int u = bid; u < 256; u += NB) {
            const int r0 = (u >> 2) * 64, n0 = (u & 3) * 64;
            __syncthreads();
            for (int t = tid; t < 1024; t += NT) {
                int rr = t >> 4, kq = (t & 15) << 2;
                *(float4*)&As64[rr][kq] = *(const float4*)&g_x1[(size_t)(r0 + rr) * 64 + kq];
                *(float4*)&Ws64[rr][kq] = *(const float4*)&l1w[(size_t)(layer * 256 + n0 + rr) * 64 + kq];
            }
            __syncthreads();
            ull acc[2][4];
#pragma unroll
            for (int i = 0; i < 2; i++)
#pragma unroll
                for (int j = 0; j < 4; j++) acc[i][j] = 0ULL;
#pragma unroll 8
            for (int kk = 0; kk < 32; kk++) {
                ull a0 = *(const ull*)&As64[ty * 2][kk * 2];
                ull a1 = *(const ull*)&As64[ty * 2 + 1][kk * 2];
                ull wv[4];
#pragma unroll
                for (int j = 0; j < 4; j++) wv[j] = *(const ull*)&Ws64[tx * 4 + j][kk * 2];
#pragma unroll
                for (int j = 0; j < 4; j++) {
                    acc[0][j] = fma2(a0, wv[j], acc[0][j]);
                    acc[1][j] = fma2(a1, wv[j], acc[1][j]);
                }
            }
#pragma unroll
            for (int i = 0; i < 2; i++) {
                int r = r0 + ty * 2 + i;
                float o[4];
#pragma unroll
                for (int j = 0; j < 4; j++) {
                    float lo, hi; unpack2(acc[i][j], lo, hi);
                    o[j] = fmaxf(lo + hi + l1b[layer * 256 + n0 + tx * 4 + j], 0.0f);
                }
                *(float4*)&g_big[(size_t)r * DFFN + n0 + tx * 4] = make_float4(o[0], o[1], o[2], o[3]);
            }
        }
        grid_sync(epoch);

        // ===== phase 5: FF2 (K=256) + residual + LN2 (+ prune/out/halfnorm on last) =====
        for (int u = bid; u < 128; u += NB) {
            const int r0 = u * 32;
            ull acc[4] = {0ULL, 0ULL, 0ULL, 0ULL};
            for (int kc = 0; kc < 256; kc += 64) {
                __syncthreads();
                for (int t = tid; t < 512; t += NT) {
                    int rr = t >> 4, kq = (t & 15) << 2;
                    *(float4*)&As32[rr][kq] = *(const float4*)&g_big[(size_t)(r0 + rr) * 256 + kc + kq];
                }
                for (int t = tid; t < 1024; t += NT) {
                    int rr = t >> 4, kq = (t & 15) << 2;
                    *(float4*)&Ws32b[rr][kq] = *(const float4*)&l2w[(size_t)(layer * 64 + rr) * 256 + kc + kq];
                }
                __syncthreads();
#pragma unroll 8
                for (int kk = 0; kk < 32; kk++) {
                    ull a = *(const ull*)&As32[ty][kk * 2];
#pragma unroll
                    for (int j = 0; j < 4; j++)
                        acc[j] = fma2(a, *(const ull*)&Ws32b[tx * 4 + j][kk * 2], acc[j]);
                }
            }
            int r = r0 + ty;
            float v[4];
#pragma unroll
            for (int j = 0; j < 4; j++) {
                int n = tx * 4 + j;
                float lo, hi; unpack2(acc[j], lo, hi);
                v[j] = lo + hi + l2b[layer * 64 + n] + g_x1[(size_t)r * 64 + n];
            }
            float s = v[0] + v[1] + v[2] + v[3];
#pragma unroll
            for (int ml = 8; ml; ml >>= 1) s += __shfl_xor_sync(0xffffffffu, s, ml, 16);
            float mu = s * (1.0f / 64.0f);
            float qv = 0.0f;
#pragma unroll
            for (int j = 0; j < 4; j++) { float d = v[j] - mu; qv += d * d; }
#pragma unroll
            for (int ml = 8; ml; ml >>= 1) qv += __shfl_xor_sync(0xffffffffu, qv, ml, 16);
            float inv = rsqrtf(qv * (1.0f / 64.0f) + LNEPS);
            float o[4], ss = 0.0f;
#pragma unroll
            for (int j = 0; j < 4; j++) {
                int n = tx * 4 + j;
                float t = (v[j] - mu) * inv * n2w[layer * 64 + n] + n2b[layer * 64 + n];
                if (last) { t *= mask[n]; ss += t * t; }
                o[j] = t;
            }
            float4 o4 = make_float4(o[0], o[1], o[2], o[3]);
            if (last) {
                *(float4*)&g_xp[(size_t)r * 64 + tx * 4] = o4;
                *(float4*)&out[(size_t)r * 64 + tx * 4] = o4;
#pragma unroll
                for (int ml = 8; ml; ml >>= 1) ss += __shfl_xor_sync(0xffffffffu, ss, ml, 16);
                if (tx == 0) g_hnx[r] = ss * (0.5f * LOG2E_F);
            } else {
                *(float4*)&g_xbuf[(size_t)r * 64 + tx * 4] = o4;
            }
        }
        grid_sync(epoch);
    }

    // ===== MMD gram phase: 8256 units (xx tri 2080 | yy tri 2080 | xy 4096) =====
    {
        float (*Bs64)[68] = Ws64;
        float* rs = smf + 8704;   // 16 warp partials
        for (int u = bid; u < 8256; u += NB) {
            const float *A, *B, *hna, *hnb;
            int bi, bj, KD; float wt; float* accp;
            if (u < 2080) {
                tri64(u, bi, bj); A = g_xp; B = g_xp; hna = g_hnx; hnb = g_hnx;
                KD = 20; wt = (bi != bj) ? 2.0f : 1.0f; accp = g_acc + 0;
            } else if (u < 4160) {
                tri64(u - 2080, bi, bj); A = rgb; B = rgb; hna = g_hny; hnb = g_hny;
                KD = 64; wt = (bi != bj) ? 2.0f : 1.0f; accp = g_acc + 1;
            } else {
                int v2 = u - 4160; bi = v2 >> 6; bj = v2 & 63;
                A = g_xp; B = rgb; hna = g_hnx; hnb = g_hny;
                KD = 20; wt = 1.0f; accp = g_acc + 2;
            }
            const int a0 = bi * 64, b0 = bj * 64;
            __syncthreads();
            for (int t = tid; t < 1024; t += NT) {
                int rr = t >> 4, kq = (t & 15) << 2;
                *(float4*)&As64[rr][kq] = *(const float4*)&A[(size_t)(a0 + rr) * 64 + kq];
                *(float4*)&Bs64[rr][kq] = *(const float4*)&B[(size_t)(b0 + rr) * 64 + kq];
            }
            __syncthreads();
            ull acc[2][4];
#pragma unroll
            for (int i = 0; i < 2; i++)
#pragma unroll
                for (int j = 0; j < 4; j++) acc[i][j] = 0ULL;
            const int KH = KD >> 1;
#pragma unroll 2
            for (int kk = 0; kk < KH; kk++) {
                ull a0v = *(const ull*)&As64[ty * 2][kk * 2];
                ull a1v = *(const ull*)&As64[ty * 2 + 1][kk * 2];
                ull bv[4];
#pragma unroll
                for (int j = 0; j < 4; j++) bv[j] = *(const ull*)&Bs64[tx * 4 + j][kk * 2];
#pragma unroll
                for (int j = 0; j < 4; j++) {
                    acc[0][j] = fma2(a0v, bv[j], acc[0][j]);
                    acc[1][j] = fma2(a1v, bv[j], acc[1][j]);
                }
            }
            float ha[2], hb[4];
#pragma unroll
            for (int i = 0; i < 2; i++) ha[i] = hna[a0 + ty * 2 + i];
#pragma unroll
            for (int j = 0; j < 4; j++) hb[j] = hnb[b0 + tx * 4 + j];
            float s = 0.0f;
#pragma unroll
            for (int i = 0; i < 2; i++)
#pragma unroll
                for (int j = 0; j < 4; j++) {
                    float lo, hi; unpack2(acc[i][j], lo, hi);
                    s += ex2f(__fmaf_rn(lo + hi, LOG2E_F, -(ha[i] + hb[j])));
                }
#pragma unroll
            for (int ml = 16; ml; ml >>= 1) s += __shfl_xor_sync(0xffffffffu, s, ml);
            if (lane == 0) rs[w] = s;
            __syncthreads();
            if (tid < 16) {
                float t = rs[tid];
#pragma unroll
                for (int ml = 8; ml; ml >>= 1) t += __shfl_xor_sync(0xffffu, t, ml, 16);
                if (tid == 0) atomicAdd(accp, t * wt);
            }
        }
    }
    grid_sync(epoch);

    if (bid == 0 && tid == 0)
        out[pos] = (g_acc[0] + g_acc[1] - 2.0f * g_acc[2]) * (1.0f / (4096.0f * 4096.0f));
}

// ---------------- host side ----------------
extern "C" void kernel_launch(void* const* d_in, const int* in_sizes, int n_in,
                              void* d_out, int out_size)
{
    const float* hsi  = (const float*)d_in[0];
    const float* rgb  = (const float*)d_in[1];
    const float* in_w = (const float*)d_in[2];
    const float* in_b = (const float*)d_in[3];
    const float* ow   = (const float*)d_in[4];
    const float* ob   = (const float*)d_in[5];
    const float* l1w  = (const float*)d_in[6];
    const float* l1b  = (const float*)d_in[7];
    const float* l2w  = (const float*)d_in[8];
    const float* l2b  = (const float*)d_in[9];
    const float* n1w  = (const float*)d_in[10];
    const float* n1b  = (const float*)d_in[11];
    const float* n2w  = (const float*)d_in[12];
    const float* n2b  = (const float*)d_in[13];
    const float* mask = (const float*)d_in[14];
    float* out = (float*)d_out;

    init_kernel<<<1, 1>>>();
    mega_kernel<<<NB, NT>>>(hsi, rgb, in_w, in_b, ow, ob, l1w, l1b, l2w, l2b,
                            n1w, n1b, n2w, n2b, mask, out, out_size - 1);
}

// round 4
// speedup vs baseline: 1.5054x; 1.5054x over previous
#include <cuda_runtime.h>

typedef unsigned long long ull;

#define MT 4096
#define DM 64
#define HDD 8
#define NLAYER 4
#define DFFN 256
#define LNEPS 1e-5f
#define LOG2E_F 1.4426950408889634f
#define QSCALE 0.35355339059327373f
#define NB 296
#define NT 256

// weight-transpose buffer offsets (floats)
#define WT_IN_OFF  0
#define WT_OUT_OFF 49152
#define WT_L1_OFF  65536
#define WT_L2_OFF  131072
#define WT_TOTAL   196608

// ---------------- device scratch ----------------
__device__ float g_wt[WT_TOTAL];
__device__ float g_xbuf[MT*DM];
__device__ float g_qh[MT*DM];
__device__ float g_kh[MT*DM];
__device__ float g_vh[MT*DM];
__device__ float g_attn[MT*DM];
__device__ float g_xp[MT*DM];
__device__ float g_hnx[MT];
__device__ float g_hny[MT];
__device__ float g_acc[3];
__device__ unsigned g_bar;

// ---------------- helpers ----------------
__device__ __forceinline__ ull fma2(ull a, ull b, ull c) {
    ull d; asm("fma.rn.f32x2 %0, %1, %2, %3;" : "=l"(d) : "l"(a), "l"(b), "l"(c)); return d;
}
__device__ __forceinline__ ull pack2(float a, float b) {
    ull r; asm("mov.b64 %0, {%1, %2};" : "=l"(r) : "f"(a), "f"(b)); return r;
}
__device__ __forceinline__ void unpack2(ull v, float& a, float& b) {
    asm("mov.b64 {%0, %1}, %2;" : "=f"(a), "=f"(b) : "l"(v));
}
__device__ __forceinline__ float ex2f(float x) {
    float r; asm("ex2.approx.f32 %0, %1;" : "=f"(r) : "f"(x)); return r;
}

__device__ __forceinline__ void grid_sync(unsigned& epoch) {
    __syncthreads();
    epoch += NB;
    if (threadIdx.x == 0) {
        __threadfence();
        atomicAdd(&g_bar, 1u);
        unsigned v;
        do {
            asm volatile("ld.acquire.gpu.global.u32 %0, [%1];" : "=r"(v) : "l"(&g_bar));
        } while (v < epoch);
    }
    __syncthreads();
}

__global__ void init_kernel() {
    g_bar = 0u;
    g_acc[0] = 0.f; g_acc[1] = 0.f; g_acc[2] = 0.f;
}

// triangular decode for 64x64 symmetric tile grid
__device__ __forceinline__ void tri64(int idx, int& bi, int& bj) {
    float fr = (129.0f - sqrtf(16641.0f - 8.0f * (float)idx)) * 0.5f;
    int r = (int)fr;
    if (r < 0) r = 0; if (r > 63) r = 63;
    while (64 * r - (r * (r - 1)) / 2 > idx) r--;
    while (64 * (r + 1) - ((r + 1) * r) / 2 <= idx) r++;
    bi = r;
    bj = r + (idx - (64 * r - (r * (r - 1)) / 2));
}

// 16-row GEMM micro: acc(2 ull = 4 cols) += A[ty][:] @ Wk (k-major, stride 68)
__device__ __forceinline__ void gemm16(const float* __restrict__ As, int strideA,
                                       const float* __restrict__ Wk,
                                       int ty, int tx, int nkk2, ull acc[2])
{
#pragma unroll 8
    for (int kk = 0; kk < nkk2; kk++) {
        ull a = *(const ull*)(As + ty * strideA + 2 * kk);
        float a0, a1; unpack2(a, a0, a1);
        ull pa0 = pack2(a0, a0), pa1 = pack2(a1, a1);
        const float* w0 = Wk + (2 * kk) * 68 + tx * 4;
        const float* w1 = w0 + 68;
        acc[0] = fma2(pa0, *(const ull*)w0,       acc[0]);
        acc[1] = fma2(pa0, *(const ull*)(w0 + 2), acc[1]);
        acc[0] = fma2(pa1, *(const ull*)w1,       acc[0]);
        acc[1] = fma2(pa1, *(const ull*)(w1 + 2), acc[1]);
    }
}

// layernorm over 16-lane row groups; v in, o out
__device__ __forceinline__ void ln16(const float v[4], const float* __restrict__ w,
                                     const float* __restrict__ b, int n0, float o[4])
{
    float s = v[0] + v[1] + v[2] + v[3];
#pragma unroll
    for (int ml = 8; ml; ml >>= 1) s += __shfl_xor_sync(0xffffffffu, s, ml, 16);
    float mu = s * (1.0f / 64.0f);
    float qv = 0.0f;
#pragma unroll
    for (int j = 0; j < 4; j++) { float d = v[j] - mu; qv += d * d; }
#pragma unroll
    for (int ml = 8; ml; ml >>= 1) qv += __shfl_xor_sync(0xffffffffu, qv, ml, 16);
    float inv = rsqrtf(qv * (1.0f / 64.0f) + LNEPS);
#pragma unroll
    for (int j = 0; j < 4; j++) o[j] = (v[j] - mu) * inv * w[n0 + j] + b[n0 + j];
}

// smem layout (floats)
#define AS_OFF 0        // 16x68
#define XS_OFF 1088     // 16x68
#define WK_OFF 2176     // 64x68
#define HS_OFF 6528     // 16x260
#define GA_OFF 0        // gram A 64x70
#define GB_OFF 4480     // gram B 64x70
#define RS_OFF 8960

__global__ void __launch_bounds__(NT, 2)
mega_kernel(const float* __restrict__ hsi, const float* __restrict__ rgb,
            const float* __restrict__ in_w, const float* __restrict__ in_b,
            const float* __restrict__ ow,   const float* __restrict__ ob,
            const float* __restrict__ l1w,  const float* __restrict__ l1b,
            const float* __restrict__ l2w,  const float* __restrict__ l2b,
            const float* __restrict__ n1w,  const float* __restrict__ n1b,
            const float* __restrict__ n2w,  const float* __restrict__ n2b,
            const float* __restrict__ mask, float* __restrict__ out, int pos)
{
    __shared__ __align__(16) float smf[10752];   // 42KB
    const int tid = threadIdx.x;
    const int bid = blockIdx.x;
    const int tx = tid & 15, ty = tid >> 4;
    const int w = tid >> 5, lane = tid & 31;
    unsigned epoch = 0;

    float* As = smf + AS_OFF;
    float* Xs = smf + XS_OFF;
    float* Wk = smf + WK_OFF;
    float* Hs = smf + HS_OFF;

    // ===== phase T: weight transpose (k-major) + rgb half-norms =====
    for (int idx = bid * NT + tid; idx < WT_TOTAL; idx += NB * NT) {
        float v;
        if (idx < WT_OUT_OFF) {
            int np = idx & 63, k = (idx >> 6) & 63, lp = idx >> 12;
            int l = lp / 3, p = lp - 3 * l;
            v = in_w[(size_t)(l * 192 + p * 64 + np) * 64 + k];
        } else if (idx < WT_L1_OFF) {
            int j = idx - WT_OUT_OFF;
            int n = j & 63, k = (j >> 6) & 63, l = j >> 12;
            v = ow[(size_t)(l * 64 + n) * 64 + k];
        } else if (idx < WT_L2_OFF) {
            int j = idx - WT_L1_OFF;
            int n = j & 255, k = (j >> 8) & 63, l = j >> 14;
            v = l1w[(size_t)(l * 256 + n) * 64 + k];
        } else {
            int j = idx - WT_L2_OFF;
            int n = j & 63, k = (j >> 6) & 255, l = j >> 14;
            v = l2w[(size_t)(l * 64 + n) * 256 + k];
        }
        g_wt[idx] = v;
    }
    for (int m = bid * NT + tid; m < MT; m += NB * NT) {
        const float4* r = (const float4*)(rgb + (size_t)m * 64);
        float s = 0.0f;
#pragma unroll
        for (int t = 0; t < 16; t++) {
            float4 v = r[t];
            s += v.x * v.x + v.y * v.y + v.z * v.z + v.w * v.w;
        }
        g_hny[m] = s * (0.5f * LOG2E_F);
    }
    grid_sync(epoch);

    // ===== phase Q0: QKV for layer 0 (256 units of 16 rows) =====
    for (int u = bid; u < 256; u += NB) {
        const int r0 = u * 16, r = r0 + ty;
        __syncthreads();
        {
            int t = tid;                        // 256 float4s
            int rr = t >> 4, kq = (t & 15) << 2;
            *(float4*)&Xs[rr * 68 + kq] = *(const float4*)&hsi[(size_t)(r0 + rr) * 64 + kq];
        }
        for (int part = 0; part < 3; part++) {
            __syncthreads();
            for (int t = tid; t < 1024; t += NT) {
                int rr = t >> 4, kq = (t & 15) << 2;
                *(float4*)&Wk[rr * 68 + kq] =
                    *(const float4*)&g_wt[WT_IN_OFF + (size_t)(part * 64 + rr) * 64 + kq];
            }
            __syncthreads();
            ull acc[2] = {0ULL, 0ULL};
            gemm16(Xs, 68, Wk, ty, tx, 32, acc);
            float qs = (part == 0) ? (QSCALE * LOG2E_F) : 1.0f;
            float o0, o1, o2, o3;
            unpack2(acc[0], o0, o1); unpack2(acc[1], o2, o3);
            const float* bb = in_b + part * 64 + tx * 4;
            float4 o4 = make_float4((o0 + bb[0]) * qs, (o1 + bb[1]) * qs,
                                    (o2 + bb[2]) * qs, (o3 + bb[3]) * qs);
            float* dst = (part == 0) ? g_qh : (part == 1) ? g_kh : g_vh;
            int h = tx >> 1, d0 = (tx & 1) * 4;
            *(float4*)&dst[((size_t)h * MT + r) * 8 + d0] = o4;
        }
    }
    grid_sync(epoch);

    for (int layer = 0; layer < NLAYER; layer++) {
        const int last = (layer == NLAYER - 1);
        const float* xin = (layer == 0) ? hsi : g_xbuf;

        // ===== attention: 256 units (32 q-blocks of 128 x 8 heads) =====
        for (int u = bid; u < 256; u += NB) {
            const int h = u & 7;
            const int q0 = (u >> 3) * 128;
            const float* Qb = g_qh + (size_t)h * MT * HDD;
            const float* Kb = g_kh + (size_t)h * MT * HDD;
            const float* Vb = g_vh + (size_t)h * MT * HDD;

            __syncthreads();     // guard smem reuse vs previous unit

            ull q[4][4], o[4][4];
            float l[4];
#pragma unroll
            for (int i = 0; i < 4; i++) {
                int qm = q0 + lane + 32 * i;
                const ull* qr = (const ull*)(Qb + (size_t)qm * 8);
#pragma unroll
                for (int j = 0; j < 4; j++) { q[i][j] = qr[j]; o[i][j] = 0ULL; }
                l[i] = 0.0f;
            }

            float* ksw = smf + w * 512;
            float* vsw = ksw + 256;

            for (int kt = w; kt < 128; kt += 8) {
                __syncwarp();
                const float4* Ks = (const float4*)(Kb + (size_t)kt * 256);
                const float4* Vs = (const float4*)(Vb + (size_t)kt * 256);
#pragma unroll
                for (int u2 = lane; u2 < 64; u2 += 32) {
                    ((float4*)ksw)[u2] = Ks[u2];
                    ((float4*)vsw)[u2] = Vs[u2];
                }
                __syncwarp();
                const ull* kq = (const ull*)ksw;
                const ull* vq = (const ull*)vsw;
#pragma unroll 2
                for (int j = 0; j < 32; j++) {
                    ull k0 = kq[4*j], k1 = kq[4*j+1], k2 = kq[4*j+2], k3 = kq[4*j+3];
                    ull v0 = vq[4*j], v1 = vq[4*j+1], v2 = vq[4*j+2], v3 = vq[4*j+3];
#pragma unroll
                    for (int i = 0; i < 4; i++) {
                        ull s0 = fma2(q[i][0], k0, fma2(q[i][2], k2, 0ULL));
                        ull s1 = fma2(q[i][1], k1, fma2(q[i][3], k3, 0ULL));
                        float a0, b0, a1, b1;
                        unpack2(s0, a0, b0); unpack2(s1, a1, b1);
                        float p = ex2f((a0 + a1) + (b0 + b1));
                        l[i] += p;
                        ull pp = pack2(p, p);
                        o[i][0] = fma2(pp, v0, o[i][0]);
                        o[i][1] = fma2(pp, v1, o[i][1]);
                        o[i][2] = fma2(pp, v2, o[i][2]);
                        o[i][3] = fma2(pp, v3, o[i][3]);
                    }
                }
            }

            __syncthreads();
            float* red  = smf;               // [8][128][9]
            float* lred = smf + 9216;        // [8][128]
#pragma unroll
            for (int i = 0; i < 4; i++) {
                int ql = lane + 32 * i;
                float* rr = red + (w * 128 + ql) * 9;
#pragma unroll
                for (int jj = 0; jj < 4; jj++) {
                    float a, b; unpack2(o[i][jj], a, b);
                    rr[2 * jj] = a; rr[2 * jj + 1] = b;
                }
                lred[w * 128 + ql] = l[i];
            }
            __syncthreads();
            if (tid < 128) {
                int qm = q0 + tid;
                float ls = 0.0f;
#pragma unroll
                for (int ww = 0; ww < 8; ww++) ls += lred[ww * 128 + tid];
                float inv = 1.0f / ls;
#pragma unroll
                for (int d = 0; d < 8; d++) {
                    float s = 0.0f;
#pragma unroll
                    for (int ww = 0; ww < 8; ww++) s += red[(ww * 128 + tid) * 9 + d];
                    g_attn[(size_t)qm * 64 + h * 8 + d] = s * inv;
                }
            }
        }
        grid_sync(epoch);

        // ===== phase B: out-proj+LN1+FF1+FF2+LN2 (+QKV next / +prune last), 256 units x 16 rows =====
        for (int u = bid; u < 256; u += NB) {
            const int r0 = u * 16, r = r0 + ty;
            __syncthreads();
            {
                int t = tid;
                int rr = t >> 4, kq = (t & 15) << 2;
                *(float4*)&As[rr * 68 + kq] = *(const float4*)&g_attn[(size_t)(r0 + rr) * 64 + kq];
            }
            for (int t = tid; t < 1024; t += NT) {
                int rr = t >> 4, kq = (t & 15) << 2;
                *(float4*)&Wk[rr * 68 + kq] =
                    *(const float4*)&g_wt[WT_OUT_OFF + (size_t)(layer * 64 + rr) * 64 + kq];
            }
            __syncthreads();

            // out-proj + resid + LN1
            ull acc[2] = {0ULL, 0ULL};
            gemm16(As, 68, Wk, ty, tx, 32, acc);
            float v[4];
            {
                float c0, c1, c2, c3;
                unpack2(acc[0], c0, c1); unpack2(acc[1], c2, c3);
                float4 rx = *(const float4*)&xin[(size_t)r * 64 + tx * 4];
                const float* bb = ob + layer * 64 + tx * 4;
                v[0] = c0 + bb[0] + rx.x; v[1] = c1 + bb[1] + rx.y;
                v[2] = c2 + bb[2] + rx.z; v[3] = c3 + bb[3] + rx.w;
            }
            float x1v[4];
            ln16(v, n1w + layer * 64, n1b + layer * 64, tx * 4, x1v);
            *(float4*)&Xs[ty * 68 + tx * 4] = make_float4(x1v[0], x1v[1], x1v[2], x1v[3]);

            // FF1 -> Hs
            for (int c = 0; c < 4; c++) {
                __syncthreads();
                for (int t = tid; t < 1024; t += NT) {
                    int rr = t >> 4, kq = (t & 15) << 2;
                    *(float4*)&Wk[rr * 68 + kq] =
                        *(const float4*)&g_wt[WT_L1_OFF + (size_t)(layer * 64 + rr) * 256 + c * 64 + kq];
                }
                __syncthreads();
                ull ah[2] = {0ULL, 0ULL};
                gemm16(Xs, 68, Wk, ty, tx, 32, ah);
                float h0, h1, h2, h3;
                unpack2(ah[0], h0, h1); unpack2(ah[1], h2, h3);
                const float* bb = l1b + layer * 256 + c * 64 + tx * 4;
                *(float4*)&Hs[ty * 260 + c * 64 + tx * 4] =
                    make_float4(fmaxf(h0 + bb[0], 0.f), fmaxf(h1 + bb[1], 0.f),
                                fmaxf(h2 + bb[2], 0.f), fmaxf(h3 + bb[3], 0.f));
            }

            // FF2 (K=256)
            ull acc2[2] = {0ULL, 0ULL};
            for (int c = 0; c < 4; c++) {
                __syncthreads();
                for (int t = tid; t < 1024; t += NT) {
                    int rr = t >> 4, kq = (t & 15) << 2;
                    *(float4*)&Wk[rr * 68 + kq] =
                        *(const float4*)&g_wt[WT_L2_OFF + (size_t)(layer * 256 + c * 64 + rr) * 64 + kq];
                }
                __syncthreads();
                gemm16(Hs + c * 64, 260, Wk, ty, tx, 32, acc2);
            }
            {
                float c0, c1, c2, c3;
                unpack2(acc2[0], c0, c1); unpack2(acc2[1], c2, c3);
                const float* bb = l2b + layer * 64 + tx * 4;
                v[0] = c0 + bb[0] + x1v[0]; v[1] = c1 + bb[1] + x1v[1];
                v[2] = c2 + bb[2] + x1v[2]; v[3] = c3 + bb[3] + x1v[3];
            }
            float xn[4];
            ln16(v, n2w + layer * 64, n2b + layer * 64, tx * 4, xn);

            if (last) {
                float ss = 0.0f;
#pragma unroll
                for (int j = 0; j < 4; j++) {
                    xn[j] *= mask[tx * 4 + j];
                    ss += xn[j] * xn[j];
                }
                float4 o4 = make_float4(xn[0], xn[1], xn[2], xn[3]);
                *(float4*)&g_xp[(size_t)r * 64 + tx * 4] = o4;
                *(float4*)&out[(size_t)r * 64 + tx * 4] = o4;
#pragma unroll
                for (int ml = 8; ml; ml >>= 1) ss += __shfl_xor_sync(0xffffffffu, ss, ml, 16);
                if (tx == 0) g_hnx[r] = ss * (0.5f * LOG2E_F);
            } else {
                float4 o4 = make_float4(xn[0], xn[1], xn[2], xn[3]);
                *(float4*)&g_xbuf[(size_t)r * 64 + tx * 4] = o4;
                *(float4*)&Xs[ty * 68 + tx * 4] = o4;      // own elements only
                // QKV for next layer
                for (int part = 0; part < 3; part++) {
                    __syncthreads();
                    for (int t = tid; t < 1024; t += NT) {
                        int rr = t >> 4, kq = (t & 15) << 2;
                        *(float4*)&Wk[rr * 68 + kq] =
                            *(const float4*)&g_wt[WT_IN_OFF +
                                (size_t)(((layer + 1) * 3 + part) * 64 + rr) * 64 + kq];
                    }
                    __syncthreads();
                    ull aq[2] = {0ULL, 0ULL};
                    gemm16(Xs, 68, Wk, ty, tx, 32, aq);
                    float qs = (part == 0) ? (QSCALE * LOG2E_F) : 1.0f;
                    float o0, o1, o2, o3;
                    unpack2(aq[0], o0, o1); unpack2(aq[1], o2, o3);
                    const float* bb = in_b + (layer + 1) * 192 + part * 64 + tx * 4;
                    float4 o4b = make_float4((o0 + bb[0]) * qs, (o1 + bb[1]) * qs,
                                             (o2 + bb[2]) * qs, (o3 + bb[3]) * qs);
                    float* dst = (part == 0) ? g_qh : (part == 1) ? g_kh : g_vh;
                    int h = tx >> 1, d0 = (tx & 1) * 4;
                    *(float4*)&dst[((size_t)h * MT + r) * 8 + d0] = o4b;
                }
            }
        }
        grid_sync(epoch);
    }

    // ===== MMD gram phase: 8256 units =====
    {
        float* GA = smf + GA_OFF;   // 64x70
        float* GB = smf + GB_OFF;   // 64x70
        float* rs = smf + RS_OFF;
        for (int u = bid; u < 8256; u += NB) {
            const float *A, *B, *hna, *hnb;
            int bi, bj, KD; float wt; float* accp;
            if (u < 2080) {
                tri64(u, bi, bj); A = g_xp; B = g_xp; hna = g_hnx; hnb = g_hnx;
                KD = 20; wt = (bi != bj) ? 2.0f : 1.0f; accp = g_acc + 0;
            } else if (u < 4160) {
                tri64(u - 2080, bi, bj); A = rgb; B = rgb; hna = g_hny; hnb = g_hny;
                KD = 64; wt = (bi != bj) ? 2.0f : 1.0f; accp = g_acc + 1;
            } else {
                int v2 = u - 4160; bi = v2 >> 6; bj = v2 & 63;
                A = g_xp; B = rgb; hna = g_hnx; hnb = g_hny;
                KD = 20; wt = 1.0f; accp = g_acc + 2;
            }
            const int a0 = bi * 64, b0 = bj * 64;
            __syncthreads();
            for (int t = tid; t < 2048; t += NT) {
                int rr = t >> 5, kq = (t & 31) << 1;
                *(float2*)&GA[rr * 70 + kq] = *(const float2*)&A[(size_t)(a0 + rr) * 64 + kq];
                *(float2*)&GB[rr * 70 + kq] = *(const float2*)&B[(size_t)(b0 + rr) * 64 + kq];
            }
            __syncthreads();
            ull acc[4][4];
#pragma unroll
            for (int i = 0; i < 4; i++)
#pragma unroll
                for (int j = 0; j < 4; j++) acc[i][j] = 0ULL;
            const int KH = KD >> 1;
#pragma unroll 2
            for (int kk = 0; kk < KH; kk++) {
                ull av[4], bv[4];
#pragma unroll
                for (int i = 0; i < 4; i++) av[i] = *(const ull*)&GA[(ty * 4 + i) * 70 + kk * 2];
#pragma unroll
                for (int j = 0; j < 4; j++) bv[j] = *(const ull*)&GB[(tx * 4 + j) * 70 + kk * 2];
#pragma unroll
                for (int i = 0; i < 4; i++)
#pragma unroll
                    for (int j = 0; j < 4; j++) acc[i][j] = fma2(av[i], bv[j], acc[i][j]);
            }
            float ha[4], hb[4];
#pragma unroll
            for (int i = 0; i < 4; i++) ha[i] = hna[a0 + ty * 4 + i];
#pragma unroll
            for (int j = 0; j < 4; j++) hb[j] = hnb[b0 + tx * 4 + j];
            float s = 0.0f;
#pragma unroll
            for (int i = 0; i < 4; i++)
#pragma unroll
                for (int j = 0; j < 4; j++) {
                    float lo, hi; unpack2(acc[i][j], lo, hi);
                    s += ex2f(__fmaf_rn(lo + hi, LOG2E_F, -(ha[i] + hb[j])));
                }
#pragma unroll
            for (int ml = 16; ml; ml >>= 1) s += __shfl_xor_sync(0xffffffffu, s, ml);
            if (lane == 0) rs[w] = s;
            __syncthreads();
            if (tid < 8) {
                float t = rs[tid];
#pragma unroll
                for (int ml = 4; ml; ml >>= 1) t += __shfl_xor_sync(0xffu, t, ml, 8);
                if (tid == 0) atomicAdd(accp, t * wt);
            }
        }
    }
    grid_sync(epoch);

    if (bid == 0 && tid == 0)
        out[pos] = (g_acc[0] + g_acc[1] - 2.0f * g_acc[2]) * (1.0f / (4096.0f * 4096.0f));
}

// ---------------- host side ----------------
extern "C" void kernel_launch(void* const* d_in, const int* in_sizes, int n_in,
                              void* d_out, int out_size)
{
    const float* hsi  = (const float*)d_in[0];
    const float* rgb  = (const float*)d_in[1];
    const float* in_w = (const float*)d_in[2];
    const float* in_b = (const float*)d_in[3];
    const float* ow   = (const float*)d_in[4];
    const float* ob   = (const float*)d_in[5];
    const float* l1w  = (const float*)d_in[6];
    const float* l1b  = (const float*)d_in[7];
    const float* l2w  = (const float*)d_in[8];
    const float* l2b  = (const float*)d_in[9];
    const float* n1w  = (const float*)d_in[10];
    const float* n1b  = (const float*)d_in[11];
    const float* n2w  = (const float*)d_in[12];
    const float* n2b  = (const float*)d_in[13];
    const float* mask = (const float*)d_in[14];
    float* out = (float*)d_out;

    init_kernel<<<1, 1>>>();
    mega_kernel<<<NB, NT>>>(hsi, rgb, in_w, in_b, ow, ob, l1w, l1b, l2w, l2b,
                            n1w, n1b, n2w, n2b, mask, out, out_size - 1);
}